// round 10
// baseline (speedup 1.0000x reference)
#include <cuda_runtime.h>
#include <float.h>

#define BB    2
#define NN    2048
#define KK    32
#define FTOT  480
#define TGRID 296   // 2 blocks/SM on 148 SMs: fully resident -> safe spin-sync

// ---------------- scratch (static device globals; no allocation) -------------
__device__ float g_D[BB * NN * NN];
__device__ int   g_idx[BB * NN * KK];
__device__ float g_P[BB * NN * 256];
__device__ float g_Q[BB * NN * 256];
__device__ float g_feats[BB * NN * FTOT];
__device__ float g_part[BB * 512 * 256 * 2];
__device__ float g_ms[BB * 256 * 2];
__device__ float g_sq[BB * NN];
__device__ float g_f[BB * NN * 128];
__device__ float g_pmax[BB * 32 * 128];
__device__ float g_Wp[43104];
__device__ float g_Wq[43104];
__device__ float g_WhT[480 * 128];
__device__ int   g_c[8];                 // monotonic phase counters (reset in final_k)

// Release-arrive + acquire-wait on a global counter. All blocks resident.
__device__ __forceinline__ void arrive_wait(int* ctr, int target, int t) {
    __threadfence();
    __syncthreads();
    if (t == 0) {
        atomicAdd(ctr, 1);
        volatile int* vp = ctr;
        while (*vp < target) __nanosleep(100);
    }
    __syncthreads();
    __threadfence();
}

// ---------------- layer-0 distance (C=3), triangular + mirror ----------------
__global__ void dist_small(const float* __restrict__ X) {
    int b = blockIdx.z;
    int p = blockIdx.x, bi = 0;
    while (p >= 32 - bi) { p -= 32 - bi; bi++; }
    int bj = bi + p;
    int i0 = bi * 64, j0 = bj * 64;
    __shared__ float sxi[3][64], sxj[3][64];
    int t = threadIdx.x;
    if (t < 64) {
        const float* s = X + ((size_t)b * NN + i0 + t) * 3;
        sxi[0][t] = s[0]; sxi[1][t] = s[1]; sxi[2][t] = s[2];
    } else if (t < 128) {
        int r = t - 64;
        const float* s = X + ((size_t)b * NN + j0 + r) * 3;
        sxj[0][r] = s[0]; sxj[1][r] = s[1]; sxj[2][r] = s[2];
    }
    __syncthreads();
    int tx = t & 15, ty = t >> 4;
    float xi0[4], xi1[4], xi2[4], xj0[4], xj1[4], xj2[4];
#pragma unroll
    for (int u = 0; u < 4; u++) {
        xi0[u] = sxi[0][ty * 4 + u]; xi1[u] = sxi[1][ty * 4 + u]; xi2[u] = sxi[2][ty * 4 + u];
        xj0[u] = sxj[0][tx * 4 + u]; xj1[u] = sxj[1][tx * 4 + u]; xj2[u] = sxj[2][tx * 4 + u];
    }
    float dv[4][4];
#pragma unroll
    for (int u = 0; u < 4; u++)
#pragma unroll
        for (int v = 0; v < 4; v++) {
            float d0 = xi0[u] - xj0[v];
            float d1 = xi1[u] - xj1[v];
            float d2 = xi2[u] - xj2[v];
            float a = fmaf(d0, d0, 0.f);
            a = fmaf(d1, d1, a);
            a = fmaf(d2, d2, a);
            dv[u][v] = a;
        }
    float* Dp = g_D + (size_t)b * NN * NN;
#pragma unroll
    for (int u = 0; u < 4; u++)
        *(float4*)(Dp + (size_t)(i0 + ty * 4 + u) * NN + j0 + tx * 4) =
            make_float4(dv[u][0], dv[u][1], dv[u][2], dv[u][3]);
    if (bi != bj) {
#pragma unroll
        for (int v = 0; v < 4; v++)
            *(float4*)(Dp + (size_t)(j0 + tx * 4 + v) * NN + i0 + ty * 4) =
                make_float4(dv[0][v], dv[1][v], dv[2][v], dv[3][v]);
    }
}

// ---------------- distance GEMM, triangular + mirror + reg prefetch ----------
__global__ void __launch_bounds__(256, 2) dist_gemm(int C, int coff) {
    int b = blockIdx.z;
    int p = blockIdx.x, bi = 0;
    while (p >= 16 - bi) { p -= 16 - bi; bi++; }
    int bj = bi + p;
    int i0 = bi * 128, j0 = bj * 128;
    __shared__ float sA[16 * 128];
    __shared__ float sB[16 * 128];
    int t = threadIdx.x;
    int w = t >> 5, l = t & 31;
    int ibase = (w >> 1) * 32 + (l >> 3) * 8;
    int jbase = (w & 1) * 64 + (l & 7) * 8;
    float acc[8][8];
#pragma unroll
    for (int u = 0; u < 8; u++)
#pragma unroll
        for (int v = 0; v < 8; v++) acc[u][v] = 0.f;

    const float* Xb = g_feats + (size_t)b * NN * FTOT + coff;
    int row = t >> 1, h = t & 1;
    const float* srcA = Xb + (size_t)(i0 + row) * FTOT + h * 8;
    const float* srcB = Xb + (size_t)(j0 + row) * FTOT + h * 8;

    float4 a0 = *(const float4*)(srcA);
    float4 a1 = *(const float4*)(srcA + 4);
    float4 b0 = *(const float4*)(srcB);
    float4 b1 = *(const float4*)(srcB + 4);

    for (int c0 = 0; c0 < C; c0 += 16) {
        int cb = h * 8;
        sA[(cb + 0) * 128 + row] = a0.x; sA[(cb + 1) * 128 + row] = a0.y;
        sA[(cb + 2) * 128 + row] = a0.z; sA[(cb + 3) * 128 + row] = a0.w;
        sA[(cb + 4) * 128 + row] = a1.x; sA[(cb + 5) * 128 + row] = a1.y;
        sA[(cb + 6) * 128 + row] = a1.z; sA[(cb + 7) * 128 + row] = a1.w;
        sB[(cb + 0) * 128 + row] = b0.x; sB[(cb + 1) * 128 + row] = b0.y;
        sB[(cb + 2) * 128 + row] = b0.z; sB[(cb + 3) * 128 + row] = b0.w;
        sB[(cb + 4) * 128 + row] = b1.x; sB[(cb + 5) * 128 + row] = b1.y;
        sB[(cb + 6) * 128 + row] = b1.z; sB[(cb + 7) * 128 + row] = b1.w;
        __syncthreads();
        if (c0 + 16 < C) {
            a0 = *(const float4*)(srcA + c0 + 16);
            a1 = *(const float4*)(srcA + c0 + 20);
            b0 = *(const float4*)(srcB + c0 + 16);
            b1 = *(const float4*)(srcB + c0 + 20);
        }
#pragma unroll
        for (int c = 0; c < 16; c++) {
            float4 xa0 = *(const float4*)&sA[c * 128 + ibase];
            float4 xa1 = *(const float4*)&sA[c * 128 + ibase + 4];
            float4 xb0 = *(const float4*)&sB[c * 128 + jbase];
            float4 xb1 = *(const float4*)&sB[c * 128 + jbase + 4];
            float av[8] = {xa0.x, xa0.y, xa0.z, xa0.w, xa1.x, xa1.y, xa1.z, xa1.w};
            float bv[8] = {xb0.x, xb0.y, xb0.z, xb0.w, xb1.x, xb1.y, xb1.z, xb1.w};
#pragma unroll
            for (int u = 0; u < 8; u++)
#pragma unroll
                for (int v = 0; v < 8; v++)
                    acc[u][v] = fmaf(av[u], bv[v], acc[u][v]);
        }
        __syncthreads();
    }

    const float* sqb = g_sq + b * NN;
    float si[8], sj[8];
#pragma unroll
    for (int u = 0; u < 8; u++) si[u] = sqb[i0 + ibase + u];
#pragma unroll
    for (int v = 0; v < 8; v++) sj[v] = sqb[j0 + jbase + v];
    float* Dp = g_D + (size_t)b * NN * NN;
#pragma unroll
    for (int u = 0; u < 8; u++) {
        int i = i0 + ibase + u;
        float dv[8];
#pragma unroll
        for (int v = 0; v < 8; v++) {
            float d = si[u] + sj[v] - 2.f * acc[u][v];
            d = (d > 0.f) ? d : 0.f;
            if (bi == bj && i == j0 + jbase + v) d = 0.f;
            dv[v] = d;
        }
        float* op = Dp + (size_t)i * NN + j0 + jbase;
        *(float4*)(op)     = make_float4(dv[0], dv[1], dv[2], dv[3]);
        *(float4*)(op + 4) = make_float4(dv[4], dv[5], dv[6], dv[7]);
    }
    if (bi != bj) {
#pragma unroll
        for (int v = 0; v < 8; v++) {
            int j = j0 + jbase + v;
            float e[8];
#pragma unroll
            for (int u = 0; u < 8; u++) {
                float d = si[u] + sj[v] - 2.f * acc[u][v];
                e[u] = (d > 0.f) ? d : 0.f;
            }
            float* op = Dp + (size_t)j * NN + i0 + ibase;
            *(float4*)(op)     = make_float4(e[0], e[1], e[2], e[3]);
            *(float4*)(op + 4) = make_float4(e[4], e[5], e[6], e[7]);
        }
    }
}

// ---------------- fused: knn_select (+pq) (+weight prep, layer 0) ------------
__global__ void select_pq(int layer, int C, int O, int Olog, int c4log,
                          int coff, int woff, int R,
                          const float* __restrict__ x, const float* __restrict__ W0,
                          const float* __restrict__ W1, const float* __restrict__ W2,
                          const float* __restrict__ W3, const float* __restrict__ Wh) {
    extern __shared__ float dsm[];
    int blk = blockIdx.x;
    int t = threadIdx.x;

    if (blk < 512) {
        int b = blk >> 8;
        int row = (blk & 255) * 8 + (t >> 5);
        int l = t & 31;
        const float* Drow = g_D + ((size_t)b * NN + row) * NN;
        float* bw = dsm + (t >> 5) * 2048;
        const float4* Drow4 = (const float4*)Drow;
        float4* bw4 = (float4*)bw;
        unsigned long long gm[8];
#pragma unroll
        for (int g = 0; g < 8; g++) gm[g] = ~0ull;
#pragma unroll
        for (int c = 0; c < 16; c++) {
            float4 v = Drow4[c * 32 + l];
            bw4[c * 32 + l] = v;
            int j0 = c * 128 + l * 4;
            unsigned long long m = gm[c >> 1];
            unsigned long long p0 =
                ((unsigned long long)__float_as_uint(v.x) << 32) | (unsigned)(j0 + 0);
            unsigned long long p1 =
                ((unsigned long long)__float_as_uint(v.y) << 32) | (unsigned)(j0 + 1);
            unsigned long long p2 =
                ((unsigned long long)__float_as_uint(v.z) << 32) | (unsigned)(j0 + 2);
            unsigned long long p3 =
                ((unsigned long long)__float_as_uint(v.w) << 32) | (unsigned)(j0 + 3);
            m = p0 < m ? p0 : m;
            m = p1 < m ? p1 : m;
            m = p2 < m ? p2 : m;
            m = p3 < m ? p3 : m;
            gm[c >> 1] = m;
        }
        int* idxo = g_idx + ((size_t)b * NN + row) * KK;
        for (int it = 0; it <= KK; it++) {
            unsigned long long m = gm[0];
#pragma unroll
            for (int g = 1; g < 8; g++) m = gm[g] < m ? gm[g] : m;
            unsigned hv = (unsigned)(m >> 32), lv = (unsigned)m;
            unsigned rmin = __reduce_min_sync(0xffffffffu, hv);
            unsigned lvm = (hv == rmin) ? lv : 0xffffffffu;
            unsigned j = __reduce_min_sync(0xffffffffu, lvm);
            if (it > 0 && l == it - 1) idxo[it - 1] = (int)j;
            int ow = (int)((j >> 2) & 31);
            int g = (int)(j >> 8);
            if (l == ow) {
                bw[j] = __int_as_float(0x7f800000);
                unsigned long long nm = ~0ull;
#pragma unroll
                for (int cc = 0; cc < 2; cc++) {
#pragma unroll
                    for (int q = 0; q < 4; q++) {
                        int jj = (2 * g + cc) * 128 + l * 4 + q;
                        float v = bw[jj];
                        unsigned long long pk =
                            ((unsigned long long)__float_as_uint(v) << 32) | (unsigned)jj;
                        nm = pk < nm ? pk : nm;
                    }
                }
#pragma unroll
                for (int gg = 0; gg < 8; gg++) if (gg == g) gm[gg] = nm;
            }
        }
        return;
    }
    blk -= 512;

    if (layer == 0) {
        if (blk < 512) {
            int b = blk >> 8;
            int row = (blk & 255) * 8 + (t >> 5);
            int o = t & 31;
            const float* xr = x + ((size_t)b * NN + row) * 3;
            float x0 = xr[0], x1 = xr[1], x2 = xr[2];
            const float* Wr = W0 + o * 6;
            float a0 = Wr[0], a1 = Wr[1], a2 = Wr[2];
            float b0 = Wr[3], b1 = Wr[4], b2 = Wr[5];
            float pv = fmaf(x0, a0, 0.f); pv = fmaf(x1, a1, pv); pv = fmaf(x2, a2, pv);
            float qv = fmaf(x0, b0 - a0, 0.f); qv = fmaf(x1, b1 - a1, qv);
            qv = fmaf(x2, b2 - a2, qv);
            int base = (b * NN + row) * 256 + o;
            g_P[base] = pv;
            g_Q[base] = qv;
        } else {
            int idx = (blk - 512) * 256 + t;
            if (idx < 2048) {
                int c = idx >> 6, o = idx & 63;
                float a = W1[o * 64 + c], bw2 = W1[o * 64 + 32 + c];
                g_Wp[96 + idx] = a; g_Wq[96 + idx] = bw2 - a;
            } else if (idx < 10240) {
                int j = idx - 2048;
                int c = j >> 7, o = j & 127;
                float a = W2[o * 128 + c], bw2 = W2[o * 128 + 64 + c];
                g_Wp[2144 + j] = a; g_Wq[2144 + j] = bw2 - a;
            } else if (idx < 43008) {
                int j = idx - 10240;
                int c = j >> 8, o = j & 255;
                float a = W3[o * 256 + c], bw2 = W3[o * 256 + 128 + c];
                g_Wp[10336 + j] = a; g_Wq[10336 + j] = bw2 - a;
            } else if (idx < 104448) {
                int j = idx - 43008;
                int c = j >> 7, o = j & 127;
                g_WhT[j] = Wh[o * 480 + c];
            }
        }
        return;
    }

    {
        float* sX = dsm;
        int rows0 = blk * R;
#pragma unroll
        for (int it = 0; it < 2; it++) {
            int idx4 = t + it * 256;
            int r = idx4 >> c4log;
            int c4 = idx4 & ((1 << c4log) - 1);
            ((float4*)sX)[idx4] =
                *(const float4*)(g_feats + (size_t)(rows0 + r) * FTOT + coff + (c4 << 2));
        }
        __syncthreads();
        int o = t & (O - 1);
        int rbase = (t >> Olog) * 16;
        const float* Wpb = g_Wp + woff;
        const float* Wqb = g_Wq + woff;
        float accP[16], accQ[16];
#pragma unroll
        for (int r = 0; r < 16; r++) { accP[r] = 0.f; accQ[r] = 0.f; }
        for (int c = 0; c < C; c += 4) {
            float wp0 = Wpb[(c + 0) * O + o], wp1 = Wpb[(c + 1) * O + o];
            float wp2 = Wpb[(c + 2) * O + o], wp3 = Wpb[(c + 3) * O + o];
            float wq0 = Wqb[(c + 0) * O + o], wq1 = Wqb[(c + 1) * O + o];
            float wq2 = Wqb[(c + 2) * O + o], wq3 = Wqb[(c + 3) * O + o];
#pragma unroll
            for (int r = 0; r < 16; r++) {
                float4 xv = *(const float4*)&sX[(rbase + r) * C + c];
                accP[r] = fmaf(xv.x, wp0, fmaf(xv.y, wp1,
                          fmaf(xv.z, wp2, fmaf(xv.w, wp3, accP[r]))));
                accQ[r] = fmaf(xv.x, wq0, fmaf(xv.y, wq1,
                          fmaf(xv.z, wq2, fmaf(xv.w, wq3, accQ[r]))));
            }
        }
#pragma unroll
        for (int r = 0; r < 16; r++) {
            size_t rowi = (size_t)(rows0 + rbase + r);
            g_P[rowi * 256 + o] = accP[r];
            g_Q[rowi * 256 + o] = accQ[r];
        }
    }
}

// ---------------- persistent tail: gstat -> stats -> normfin (one launch) ----
// grid TGRID (fully resident); phases separated by counter barriers.
__global__ void __launch_bounds__(256, 4)
tail_k(int Olog, int O, int ooff, int RPB, int ngs, float inv_cnt, int tgt) {
    int t = threadIdx.x, bid = blockIdx.x;
    __shared__ int   sidx[256];
    __shared__ float rs[256], rss[256];

    // ---- Phase A: gstat (work-strided) ----
    for (int chunk = bid; chunk < ngs * BB; chunk += TGRID) {
        int b = chunk / ngs, gblk = chunk % ngs;
        int i0 = gblk * RPB;
        int o = t & (O - 1), r = t >> Olog;
        int nr = 256 >> Olog;
        for (int u = t; u < RPB * KK; u += 256)
            sidx[u] = g_idx[((size_t)b * NN + i0 + (u >> 5)) * KK + (u & 31)];
        __syncthreads();
        const float* Pb = g_P + (size_t)b * NN * 256;
        float ts = 0.f, tss = 0.f;
        for (int ii = r; ii < RPB; ii += nr) {
            int i = i0 + ii;
            float s1 = 0.f, s2 = 0.f, m = -FLT_MAX;
#pragma unroll
            for (int k = 0; k < KK; k++) {
                int j = sidx[ii * KK + k];
                float p = Pb[(size_t)j * 256 + o];
                s1 += p; s2 = fmaf(p, p, s2); m = fmaxf(m, p);
            }
            float q = g_Q[((size_t)b * NN + i) * 256 + o];
            g_feats[((size_t)b * NN + i) * FTOT + ooff + o] = q + m;
            ts  += fmaf((float)KK, q, s1);
            tss += fmaf(fmaf((float)KK, q, 2.f * s1), q, s2);
        }
        rs[t] = ts; rss[t] = tss;
        __syncthreads();
        if (t < O) {
            for (int m2 = 1; m2 < nr; m2++) {
                ts += rs[t + (m2 << Olog)]; tss += rss[t + (m2 << Olog)];
            }
            int p = ((b * 512 + gblk) * 256 + t) * 2;
            g_part[p] = ts; g_part[p + 1] = tss;
        }
        __syncthreads();
    }
    arrive_wait(&g_c[0], tgt, t);

    // ---- Phase B: stats, warp per channel ----
    {
        int gw = bid * 8 + (t >> 5), l = t & 31;
        const float2* part2 = (const float2*)g_part;
        for (int ch = gw; ch < O * BB; ch += TGRID * 8) {
            int b = ch >> Olog, o = ch & (O - 1);
            float s = 0.f, ss = 0.f;
            for (int blk = l; blk < ngs; blk += 32) {
                float2 v = part2[((size_t)b * 512 + blk) * 256 + o];
                s += v.x; ss += v.y;
            }
#pragma unroll
            for (int off = 16; off; off >>= 1) {
                s += __shfl_xor_sync(0xffffffffu, s, off);
                ss += __shfl_xor_sync(0xffffffffu, ss, off);
            }
            if (l == 0) {
                float mean = s * inv_cnt;
                float var = ss * inv_cnt - mean * mean;
                var = fmaxf(var, 0.f);
                float rstd = rsqrtf(var + 1e-5f);
                g_ms[(b * 256 + o) * 2] = mean;
                g_ms[(b * 256 + o) * 2 + 1] = rstd;
            }
        }
    }
    arrive_wait(&g_c[1], tgt, t);

    // ---- Phase C: normfin + next-layer sq ----
    {
        int w = t >> 5, l = t & 31;
        int O4 = O >> 2;
        for (int chunk = bid; chunk < (NN / 8) * BB; chunk += TGRID) {
            int b = chunk >> 8;
            int row = (chunk & 255) * 8 + w;
            float* base = g_feats + ((size_t)b * NN + row) * FTOT + ooff;
            const float2* ms2 = (const float2*)g_ms + b * 256;
            float ssq = 0.f;
            for (int c4 = l; c4 < O4; c4 += 32) {
                int o = c4 * 4;
                float4 v = *(float4*)(base + o);
                float2 m0 = ms2[o], m1 = ms2[o + 1], m2 = ms2[o + 2], m3 = ms2[o + 3];
                v.x = (v.x - m0.x) * m0.y; v.x = (v.x < 0.f) ? 0.2f * v.x : v.x;
                v.y = (v.y - m1.x) * m1.y; v.y = (v.y < 0.f) ? 0.2f * v.y : v.y;
                v.z = (v.z - m2.x) * m2.y; v.z = (v.z < 0.f) ? 0.2f * v.z : v.z;
                v.w = (v.w - m3.x) * m3.y; v.w = (v.w < 0.f) ? 0.2f * v.w : v.w;
                *(float4*)(base + o) = v;
                ssq = fmaf(v.x, v.x, ssq); ssq = fmaf(v.y, v.y, ssq);
                ssq = fmaf(v.z, v.z, ssq); ssq = fmaf(v.w, v.w, ssq);
            }
#pragma unroll
            for (int off = 16; off; off >>= 1)
                ssq += __shfl_xor_sync(0xffffffffu, ssq, off);
            if (l == 0) g_sq[b * NN + row] = ssq;
        }
    }
}

// ---------------- persistent final: fconv -> stats -> fpmax -> head ----------
__global__ void __launch_bounds__(256, 4)
final_k(const float* __restrict__ fc1w, const float* __restrict__ fc1b,
        const float* __restrict__ fc2w, const float* __restrict__ fc2b,
        float* __restrict__ out) {
    int t = threadIdx.x, bid = blockIdx.x;
    __shared__ float4 sf4[8 * 120];
    __shared__ float sps[256], spss[256];
    __shared__ float sg[128], sh[128], r1[128], r2[128];

    // ---- Phase A: fconv, 8 rows per chunk; 256 threads = (o, half) ----
    {
        int o = t & 127, hf = t >> 7;
        for (int chunk = bid; chunk < 512; chunk += TGRID) {
            int b = chunk >> 8, fb = chunk & 255;
            int i0 = fb * 8;
            for (int i4 = t; i4 < 960; i4 += 256) {
                int r = i4 / 120, c4 = i4 % 120;
                sf4[r * 120 + c4] = ((const float4*)(g_feats +
                    ((size_t)b * NN + i0 + r) * FTOT))[c4];
            }
            __syncthreads();
            float acc[4];
#pragma unroll
            for (int r = 0; r < 4; r++) acc[r] = 0.f;
            for (int c4 = 0; c4 < 120; c4++) {
                int c = c4 * 4;
                float w0 = g_WhT[(c + 0) * 128 + o];
                float w1 = g_WhT[(c + 1) * 128 + o];
                float w2 = g_WhT[(c + 2) * 128 + o];
                float w3 = g_WhT[(c + 3) * 128 + o];
#pragma unroll
                for (int r = 0; r < 4; r++) {
                    float4 xv = sf4[(hf * 4 + r) * 120 + c4];
                    acc[r] = fmaf(xv.x, w0, fmaf(xv.y, w1,
                             fmaf(xv.z, w2, fmaf(xv.w, w3, acc[r]))));
                }
            }
            float s = 0.f, ss = 0.f;
#pragma unroll
            for (int r = 0; r < 4; r++) {
                g_f[((size_t)b * NN + i0 + hf * 4 + r) * 128 + o] = acc[r];
                s += acc[r];
                ss = fmaf(acc[r], acc[r], ss);
            }
            sps[t] = s; spss[t] = ss;
            __syncthreads();
            if (hf == 0) {
                s += sps[t + 128]; ss += spss[t + 128];
                int p = ((b * 512 + fb) * 256 + o) * 2;
                g_part[p] = s; g_part[p + 1] = ss;
            }
            __syncthreads();
        }
    }
    arrive_wait(&g_c[2], TGRID, t);

    // ---- Phase B: stats, warp per channel (256 channels) ----
    {
        int gw = bid * 8 + (t >> 5), l = t & 31;
        const float2* part2 = (const float2*)g_part;
        for (int ch = gw; ch < 256; ch += TGRID * 8) {
            int b = ch >> 7, o = ch & 127;
            float s = 0.f, ss = 0.f;
            for (int blk = l; blk < 256; blk += 32) {
                float2 v = part2[((size_t)b * 512 + blk) * 256 + o];
                s += v.x; ss += v.y;
            }
#pragma unroll
            for (int off = 16; off; off >>= 1) {
                s += __shfl_xor_sync(0xffffffffu, s, off);
                ss += __shfl_xor_sync(0xffffffffu, ss, off);
            }
            if (l == 0) {
                float mean = s * (1.f / (float)NN);
                float var = ss * (1.f / (float)NN) - mean * mean;
                var = fmaxf(var, 0.f);
                float rstd = rsqrtf(var + 1e-5f);
                g_ms[(b * 256 + o) * 2] = mean;
                g_ms[(b * 256 + o) * 2 + 1] = rstd;
            }
        }
    }
    arrive_wait(&g_c[3], TGRID, t);

    // ---- Phase C: fpmax partials, 64 chunks ----
    {
        int o = t & 127, hf = t >> 7;
        for (int chunk = bid; chunk < 64; chunk += TGRID) {
            int b = chunk >> 5, k = chunk & 31;
            float mean = g_ms[(b * 256 + o) * 2];
            float rstd = g_ms[(b * 256 + o) * 2 + 1];
            float m = -FLT_MAX;
            int i0 = k * 64 + hf * 32;
#pragma unroll 8
            for (int i = i0; i < i0 + 32; i++) {
                float v = (g_f[((size_t)b * NN + i) * 128 + o] - mean) * rstd;
                v = (v < 0.f) ? 0.2f * v : v;
                m = fmaxf(m, v);
            }
            sps[t] = m;
            __syncthreads();
            if (hf == 0)
                g_pmax[(b * 32 + k) * 128 + o] = fmaxf(sps[t], sps[t + 128]);
            __syncthreads();
        }
    }
    arrive_wait(&g_c[4], TGRID, t);

    // ---- Phase D: head (block 0 only) + counter reset ----
    if (bid == 0) {
        int o = t;
        float acc = 0.f;
        for (int bb = 0; bb < BB; bb++) {
            if (o < 128) {
                float mm = -FLT_MAX;
#pragma unroll
                for (int k = 0; k < 32; k++)
                    mm = fmaxf(mm, g_pmax[(bb * 32 + k) * 128 + o]);
                sg[o] = mm;
            }
            __syncthreads();
            if (o < 128) {
                acc = fc1b[o];
#pragma unroll 8
                for (int c = 0; c < 128; c++)
                    acc = fmaf(fc1w[o * 128 + c], sg[c], acc);
                r1[o] = acc;
                r2[o] = acc * acc;
            }
            __syncthreads();
            for (int s = 64; s > 0; s >>= 1) {
                if (o < s) { r1[o] += r1[o + s]; r2[o] += r2[o + s]; }
                __syncthreads();
            }
            float mean2 = r1[0] * (1.f / 128.f);
            float var = r2[0] * (1.f / 128.f) - mean2 * mean2;
            float rstd2 = rsqrtf(fmaxf(var, 0.f) + 1e-5f);
            if (o < 128) {
                float v = (acc - mean2) * rstd2;
                v = (v < 0.f) ? 0.2f * v : v;
                sh[o] = v;
            }
            __syncthreads();
            if (o < 128) {
                float outv = fc2b[o];
#pragma unroll 8
                for (int c = 0; c < 128; c++)
                    outv = fmaf(fc2w[o * 128 + c], sh[c], outv);
                out[bb * 128 + o] = outv;
            }
            __syncthreads();
        }
        if (t == 0) {                         // reset for next graph replay
            g_c[0] = 0; g_c[1] = 0; g_c[2] = 0; g_c[3] = 0; g_c[4] = 0;
        }
    }
}

// -----------------------------------------------------------------------------
extern "C" void kernel_launch(void* const* d_in, const int* in_sizes, int n_in,
                              void* d_out, int out_size) {
    (void)in_sizes; (void)n_in; (void)out_size;
    const float* x    = (const float*)d_in[0];
    const float* W[4] = {(const float*)d_in[2], (const float*)d_in[3],
                         (const float*)d_in[4], (const float*)d_in[5]};
    const float* Wh   = (const float*)d_in[6];
    const float* fc1w = (const float*)d_in[7];
    const float* fc1b = (const float*)d_in[8];
    const float* fc2w = (const float*)d_in[9];
    const float* fc2b = (const float*)d_in[10];

    const int Cin[4]  = {3, 32, 64, 128};
    const int Oo[4]   = {32, 64, 128, 256};
    const int Olg[4]  = {5, 6, 7, 8};
    const int C4lg[4] = {0, 3, 4, 5};
    const int coff[4] = {0, 0, 32, 96};
    const int ooff[4] = {0, 32, 96, 224};
    const int woff[4] = {0, 96, 2144, 10336};
    const int RPB[4]  = {8, 8, 4, 4};
    const float invNK = 1.f / (float)(NN * KK);

    static int smem_set = 0;
    if (!smem_set) {
        cudaFuncSetAttribute(select_pq, cudaFuncAttributeMaxDynamicSharedMemorySize,
                             65536);
        smem_set = 1;
    }

    for (int l = 0; l < 4; l++) {
        if (l == 0) {
            dist_small<<<dim3(528, 1, BB), 256>>>(x);
        } else {
            dist_gemm<<<dim3(136, 1, BB), 256>>>(Cin[l], coff[l]);
        }
        int R = 16 * (256 >> Olg[l]);
        int npq = (l == 0) ? 512 : (BB * NN) / R;
        int nprep = (l == 0) ? 408 : 0;
        select_pq<<<512 + npq + nprep, 256, 65536>>>(
            l, Cin[l], Oo[l], Olg[l], C4lg[l], coff[l], woff[l], R,
            x, W[0], W[1], W[2], W[3], Wh);
        int ngs = NN / RPB[l];
        tail_k<<<TGRID, 256>>>(Olg[l], Oo[l], ooff[l], RPB[l], ngs, invNK,
                               TGRID * (l + 1));
    }
    final_k<<<TGRID, 256>>>(fc1w, fc1b, fc2w, fc2b, (float*)d_out);
}

// round 11
// speedup vs baseline: 1.0723x; 1.0723x over previous
#include <cuda_runtime.h>
#include <cuda_device_runtime_api.h>
#include <float.h>

#define BB   2
#define NN   2048
#define KK   32
#define FTOT 480

// PDL entry: all CTAs trigger (allows next kernel's CTAs to pre-launch),
// then wait for full completion+visibility of the upstream grid.
#define PDL_SYNC() do { \
    cudaTriggerProgrammaticLaunchCompletion(); \
    cudaGridDependencySynchronize(); \
} while (0)

// ---------------- scratch (static device globals; no allocation) -------------
__device__ float g_D[BB * NN * NN];          // 33.5 MB pairwise distances
__device__ int   g_idx[BB * NN * KK];        // knn indices (self removed)
__device__ float g_P[BB * NN * 256];         // x . A^T   (neighbor term)
__device__ float g_Q[BB * NN * 256];         // x . (B-A)^T (center term)
__device__ float g_feats[BB * NN * FTOT];    // concat of layer outputs
__device__ float g_part[BB * 512 * 256 * 2]; // per-block partial (sum, sumsq)
__device__ float g_ms[BB * 256 * 2];         // per-channel (mean, rstd)
__device__ float g_sq[BB * NN];              // squared norms for GEMM distance
__device__ float g_f[BB * NN * 128];         // head conv output
__device__ float g_pmax[BB * 32 * 128];      // partial max for pooling
__device__ float g_Wp[43104];                // transposed A weights, all layers
__device__ float g_Wq[43104];                // transposed (B-A) weights
__device__ float g_WhT[480 * 128];           // transposed head conv weight

// ---------------- layer-0 distance (C=3), triangular + mirror ----------------
__global__ void dist_small(const float* __restrict__ X) {
    PDL_SYNC();
    int b = blockIdx.z;
    int p = blockIdx.x, bi = 0;
    while (p >= 32 - bi) { p -= 32 - bi; bi++; }
    int bj = bi + p;
    int i0 = bi * 64, j0 = bj * 64;
    __shared__ float sxi[3][64], sxj[3][64];
    int t = threadIdx.x;
    if (t < 64) {
        const float* s = X + ((size_t)b * NN + i0 + t) * 3;
        sxi[0][t] = s[0]; sxi[1][t] = s[1]; sxi[2][t] = s[2];
    } else if (t < 128) {
        int r = t - 64;
        const float* s = X + ((size_t)b * NN + j0 + r) * 3;
        sxj[0][r] = s[0]; sxj[1][r] = s[1]; sxj[2][r] = s[2];
    }
    __syncthreads();
    int tx = t & 15, ty = t >> 4;
    float xi0[4], xi1[4], xi2[4], xj0[4], xj1[4], xj2[4];
#pragma unroll
    for (int u = 0; u < 4; u++) {
        xi0[u] = sxi[0][ty * 4 + u]; xi1[u] = sxi[1][ty * 4 + u]; xi2[u] = sxi[2][ty * 4 + u];
        xj0[u] = sxj[0][tx * 4 + u]; xj1[u] = sxj[1][tx * 4 + u]; xj2[u] = sxj[2][tx * 4 + u];
    }
    float dv[4][4];
#pragma unroll
    for (int u = 0; u < 4; u++)
#pragma unroll
        for (int v = 0; v < 4; v++) {
            float d0 = xi0[u] - xj0[v];
            float d1 = xi1[u] - xj1[v];
            float d2 = xi2[u] - xj2[v];
            float a = fmaf(d0, d0, 0.f);
            a = fmaf(d1, d1, a);
            a = fmaf(d2, d2, a);
            dv[u][v] = a;
        }
    float* Dp = g_D + (size_t)b * NN * NN;
#pragma unroll
    for (int u = 0; u < 4; u++)
        *(float4*)(Dp + (size_t)(i0 + ty * 4 + u) * NN + j0 + tx * 4) =
            make_float4(dv[u][0], dv[u][1], dv[u][2], dv[u][3]);
    if (bi != bj) {
#pragma unroll
        for (int v = 0; v < 4; v++)
            *(float4*)(Dp + (size_t)(j0 + tx * 4 + v) * NN + i0 + ty * 4) =
                make_float4(dv[0][v], dv[1][v], dv[2][v], dv[3][v]);
    }
}

// ---------------- distance GEMM, triangular + mirror + reg prefetch ----------
__global__ void __launch_bounds__(256, 2) dist_gemm(int C, int coff) {
    PDL_SYNC();
    int b = blockIdx.z;
    int p = blockIdx.x, bi = 0;
    while (p >= 16 - bi) { p -= 16 - bi; bi++; }
    int bj = bi + p;
    int i0 = bi * 128, j0 = bj * 128;
    __shared__ float sA[16 * 128];
    __shared__ float sB[16 * 128];
    int t = threadIdx.x;
    int w = t >> 5, l = t & 31;
    int ibase = (w >> 1) * 32 + (l >> 3) * 8;
    int jbase = (w & 1) * 64 + (l & 7) * 8;
    float acc[8][8];
#pragma unroll
    for (int u = 0; u < 8; u++)
#pragma unroll
        for (int v = 0; v < 8; v++) acc[u][v] = 0.f;

    const float* Xb = g_feats + (size_t)b * NN * FTOT + coff;
    int row = t >> 1, h = t & 1;
    const float* srcA = Xb + (size_t)(i0 + row) * FTOT + h * 8;
    const float* srcB = Xb + (size_t)(j0 + row) * FTOT + h * 8;

    float4 a0 = *(const float4*)(srcA);
    float4 a1 = *(const float4*)(srcA + 4);
    float4 b0 = *(const float4*)(srcB);
    float4 b1 = *(const float4*)(srcB + 4);

    for (int c0 = 0; c0 < C; c0 += 16) {
        int cb = h * 8;
        sA[(cb + 0) * 128 + row] = a0.x; sA[(cb + 1) * 128 + row] = a0.y;
        sA[(cb + 2) * 128 + row] = a0.z; sA[(cb + 3) * 128 + row] = a0.w;
        sA[(cb + 4) * 128 + row] = a1.x; sA[(cb + 5) * 128 + row] = a1.y;
        sA[(cb + 6) * 128 + row] = a1.z; sA[(cb + 7) * 128 + row] = a1.w;
        sB[(cb + 0) * 128 + row] = b0.x; sB[(cb + 1) * 128 + row] = b0.y;
        sB[(cb + 2) * 128 + row] = b0.z; sB[(cb + 3) * 128 + row] = b0.w;
        sB[(cb + 4) * 128 + row] = b1.x; sB[(cb + 5) * 128 + row] = b1.y;
        sB[(cb + 6) * 128 + row] = b1.z; sB[(cb + 7) * 128 + row] = b1.w;
        __syncthreads();
        if (c0 + 16 < C) {
            a0 = *(const float4*)(srcA + c0 + 16);
            a1 = *(const float4*)(srcA + c0 + 20);
            b0 = *(const float4*)(srcB + c0 + 16);
            b1 = *(const float4*)(srcB + c0 + 20);
        }
#pragma unroll
        for (int c = 0; c < 16; c++) {
            float4 xa0 = *(const float4*)&sA[c * 128 + ibase];
            float4 xa1 = *(const float4*)&sA[c * 128 + ibase + 4];
            float4 xb0 = *(const float4*)&sB[c * 128 + jbase];
            float4 xb1 = *(const float4*)&sB[c * 128 + jbase + 4];
            float av[8] = {xa0.x, xa0.y, xa0.z, xa0.w, xa1.x, xa1.y, xa1.z, xa1.w};
            float bv[8] = {xb0.x, xb0.y, xb0.z, xb0.w, xb1.x, xb1.y, xb1.z, xb1.w};
#pragma unroll
            for (int u = 0; u < 8; u++)
#pragma unroll
                for (int v = 0; v < 8; v++)
                    acc[u][v] = fmaf(av[u], bv[v], acc[u][v]);
        }
        __syncthreads();
    }

    const float* sqb = g_sq + b * NN;
    float si[8], sj[8];
#pragma unroll
    for (int u = 0; u < 8; u++) si[u] = sqb[i0 + ibase + u];
#pragma unroll
    for (int v = 0; v < 8; v++) sj[v] = sqb[j0 + jbase + v];
    float* Dp = g_D + (size_t)b * NN * NN;
#pragma unroll
    for (int u = 0; u < 8; u++) {
        int i = i0 + ibase + u;
        float dv[8];
#pragma unroll
        for (int v = 0; v < 8; v++) {
            float d = si[u] + sj[v] - 2.f * acc[u][v];
            d = (d > 0.f) ? d : 0.f;
            if (bi == bj && i == j0 + jbase + v) d = 0.f;
            dv[v] = d;
        }
        float* op = Dp + (size_t)i * NN + j0 + jbase;
        *(float4*)(op)     = make_float4(dv[0], dv[1], dv[2], dv[3]);
        *(float4*)(op + 4) = make_float4(dv[4], dv[5], dv[6], dv[7]);
    }
    if (bi != bj) {
#pragma unroll
        for (int v = 0; v < 8; v++) {
            int j = j0 + jbase + v;
            float e[8];
#pragma unroll
            for (int u = 0; u < 8; u++) {
                float d = si[u] + sj[v] - 2.f * acc[u][v];
                e[u] = (d > 0.f) ? d : 0.f;
            }
            float* op = Dp + (size_t)j * NN + i0 + ibase;
            *(float4*)(op)     = make_float4(e[0], e[1], e[2], e[3]);
            *(float4*)(op + 4) = make_float4(e[4], e[5], e[6], e[7]);
        }
    }
}

// ---------------- fused: knn_select (+pq) (+weight prep, layer 0) ------------
__global__ void select_pq(int layer, int C, int O, int Olog, int c4log,
                          int coff, int woff, int R,
                          const float* __restrict__ x, const float* __restrict__ W0,
                          const float* __restrict__ W1, const float* __restrict__ W2,
                          const float* __restrict__ W3, const float* __restrict__ Wh) {
    PDL_SYNC();
    extern __shared__ float dsm[];
    int blk = blockIdx.x;
    int t = threadIdx.x;

    if (blk < 512) {
        // -------- select: warp per row; float4 row load; redux extraction ----
        int b = blk >> 8;
        int row = (blk & 255) * 8 + (t >> 5);
        int l = t & 31;
        const float* Drow = g_D + ((size_t)b * NN + row) * NN;
        float* bw = dsm + (t >> 5) * 2048;
        const float4* Drow4 = (const float4*)Drow;
        float4* bw4 = (float4*)bw;
        unsigned long long gm[8];
#pragma unroll
        for (int g = 0; g < 8; g++) gm[g] = ~0ull;
#pragma unroll
        for (int c = 0; c < 16; c++) {
            float4 v = Drow4[c * 32 + l];
            bw4[c * 32 + l] = v;
            int j0 = c * 128 + l * 4;
            unsigned long long m = gm[c >> 1];
            unsigned long long p0 =
                ((unsigned long long)__float_as_uint(v.x) << 32) | (unsigned)(j0 + 0);
            unsigned long long p1 =
                ((unsigned long long)__float_as_uint(v.y) << 32) | (unsigned)(j0 + 1);
            unsigned long long p2 =
                ((unsigned long long)__float_as_uint(v.z) << 32) | (unsigned)(j0 + 2);
            unsigned long long p3 =
                ((unsigned long long)__float_as_uint(v.w) << 32) | (unsigned)(j0 + 3);
            m = p0 < m ? p0 : m;
            m = p1 < m ? p1 : m;
            m = p2 < m ? p2 : m;
            m = p3 < m ? p3 : m;
            gm[c >> 1] = m;
        }
        int* idxo = g_idx + ((size_t)b * NN + row) * KK;
        for (int it = 0; it <= KK; it++) {
            unsigned long long m = gm[0];
#pragma unroll
            for (int g = 1; g < 8; g++) m = gm[g] < m ? gm[g] : m;
            unsigned hv = (unsigned)(m >> 32), lv = (unsigned)m;
            unsigned rmin = __reduce_min_sync(0xffffffffu, hv);
            unsigned lvm = (hv == rmin) ? lv : 0xffffffffu;
            unsigned j = __reduce_min_sync(0xffffffffu, lvm);
            if (it > 0 && l == it - 1) idxo[it - 1] = (int)j;
            int ow = (int)((j >> 2) & 31);   // loader lane owns eviction
            int g = (int)(j >> 8);
            if (l == ow) {
                bw[j] = __int_as_float(0x7f800000);
                unsigned long long nm = ~0ull;
#pragma unroll
                for (int cc = 0; cc < 2; cc++) {
#pragma unroll
                    for (int q = 0; q < 4; q++) {
                        int jj = (2 * g + cc) * 128 + l * 4 + q;
                        float v = bw[jj];
                        unsigned long long pk =
                            ((unsigned long long)__float_as_uint(v) << 32) | (unsigned)jj;
                        nm = pk < nm ? pk : nm;
                    }
                }
#pragma unroll
                for (int gg = 0; gg < 8; gg++) if (gg == g) gm[gg] = nm;
            }
        }
        return;
    }
    blk -= 512;

    if (layer == 0) {
        if (blk < 512) {
            int b = blk >> 8;
            int row = (blk & 255) * 8 + (t >> 5);
            int o = t & 31;
            const float* xr = x + ((size_t)b * NN + row) * 3;
            float x0 = xr[0], x1 = xr[1], x2 = xr[2];
            const float* Wr = W0 + o * 6;
            float a0 = Wr[0], a1 = Wr[1], a2 = Wr[2];
            float b0 = Wr[3], b1 = Wr[4], b2 = Wr[5];
            float pv = fmaf(x0, a0, 0.f); pv = fmaf(x1, a1, pv); pv = fmaf(x2, a2, pv);
            float qv = fmaf(x0, b0 - a0, 0.f); qv = fmaf(x1, b1 - a1, qv);
            qv = fmaf(x2, b2 - a2, qv);
            int base = (b * NN + row) * 256 + o;
            g_P[base] = pv;
            g_Q[base] = qv;
        } else {
            int idx = (blk - 512) * 256 + t;
            if (idx < 2048) {
                int c = idx >> 6, o = idx & 63;
                float a = W1[o * 64 + c], bw2 = W1[o * 64 + 32 + c];
                g_Wp[96 + idx] = a; g_Wq[96 + idx] = bw2 - a;
            } else if (idx < 10240) {
                int j = idx - 2048;
                int c = j >> 7, o = j & 127;
                float a = W2[o * 128 + c], bw2 = W2[o * 128 + 64 + c];
                g_Wp[2144 + j] = a; g_Wq[2144 + j] = bw2 - a;
            } else if (idx < 43008) {
                int j = idx - 10240;
                int c = j >> 8, o = j & 255;
                float a = W3[o * 256 + c], bw2 = W3[o * 256 + 128 + c];
                g_Wp[10336 + j] = a; g_Wq[10336 + j] = bw2 - a;
            } else if (idx < 104448) {
                int j = idx - 43008;
                int c = j >> 7, o = j & 127;
                g_WhT[j] = Wh[o * 480 + c];
            }
        }
        return;
    }

    // -------- pq_gemm: layers 1-3, transposed weights --------
    {
        float* sX = dsm;
        int rows0 = blk * R;
#pragma unroll
        for (int it = 0; it < 2; it++) {
            int idx4 = t + it * 256;
            int r = idx4 >> c4log;
            int c4 = idx4 & ((1 << c4log) - 1);
            ((float4*)sX)[idx4] =
                *(const float4*)(g_feats + (size_t)(rows0 + r) * FTOT + coff + (c4 << 2));
        }
        __syncthreads();
        int o = t & (O - 1);
        int rbase = (t >> Olog) * 16;
        const float* Wpb = g_Wp + woff;
        const float* Wqb = g_Wq + woff;
        float accP[16], accQ[16];
#pragma unroll
        for (int r = 0; r < 16; r++) { accP[r] = 0.f; accQ[r] = 0.f; }
        for (int c = 0; c < C; c += 4) {
            float wp0 = Wpb[(c + 0) * O + o], wp1 = Wpb[(c + 1) * O + o];
            float wp2 = Wpb[(c + 2) * O + o], wp3 = Wpb[(c + 3) * O + o];
            float wq0 = Wqb[(c + 0) * O + o], wq1 = Wqb[(c + 1) * O + o];
            float wq2 = Wqb[(c + 2) * O + o], wq3 = Wqb[(c + 3) * O + o];
#pragma unroll
            for (int r = 0; r < 16; r++) {
                float4 xv = *(const float4*)&sX[(rbase + r) * C + c];
                accP[r] = fmaf(xv.x, wp0, fmaf(xv.y, wp1,
                          fmaf(xv.z, wp2, fmaf(xv.w, wp3, accP[r]))));
                accQ[r] = fmaf(xv.x, wq0, fmaf(xv.y, wq1,
                          fmaf(xv.z, wq2, fmaf(xv.w, wq3, accQ[r]))));
            }
        }
#pragma unroll
        for (int r = 0; r < 16; r++) {
            size_t rowi = (size_t)(rows0 + rbase + r);
            g_P[rowi * 256 + o] = accP[r];
            g_Q[rowi * 256 + o] = accQ[r];
        }
    }
}

// ---------------- fused gather: stats partials + raw max ---------------------
__global__ void gstat(int Olog, int O, int ooff, int RPB) {
    PDL_SYNC();
    int b = blockIdx.y, i0 = blockIdx.x * RPB, t = threadIdx.x;
    int o = t & (O - 1), r = t >> Olog;
    int nr = 256 >> Olog;
    __shared__ int sidx[256];
    for (int u = t; u < RPB * KK; u += 256)
        sidx[u] = g_idx[((size_t)b * NN + i0 + (u >> 5)) * KK + (u & 31)];
    __syncthreads();
    const float* Pb = g_P + (size_t)b * NN * 256;
    float ts = 0.f, tss = 0.f;
    for (int ii = r; ii < RPB; ii += nr) {
        int i = i0 + ii;
        float s1 = 0.f, s2 = 0.f, m = -FLT_MAX;
#pragma unroll
        for (int k = 0; k < KK; k++) {
            int j = sidx[ii * KK + k];
            float p = Pb[(size_t)j * 256 + o];
            s1 += p; s2 = fmaf(p, p, s2); m = fmaxf(m, p);
        }
        float q = g_Q[((size_t)b * NN + i) * 256 + o];
        g_feats[((size_t)b * NN + i) * FTOT + ooff + o] = q + m;
        ts  += fmaf((float)KK, q, s1);
        tss += fmaf(fmaf((float)KK, q, 2.f * s1), q, s2);
    }
    __shared__ float rs[256], rss[256];
    rs[t] = ts; rss[t] = tss;
    __syncthreads();
    if (t < O) {
        for (int m2 = 1; m2 < nr; m2++) {
            ts += rs[t + (m2 << Olog)]; tss += rss[t + (m2 << Olog)];
        }
        int p = ((b * 512 + blockIdx.x) * 256 + t) * 2;
        g_part[p] = ts; g_part[p + 1] = tss;
    }
}

// ---------------- stats finalize: grid (O/32, B), 256 threads ----------------
__global__ void stats_final(int nblk, float inv_cnt) {
    PDL_SYNC();
    int b = blockIdx.y;
    int o = blockIdx.x * 32 + (threadIdx.x & 31);
    int g = threadIdx.x >> 5;
    const float2* part2 = (const float2*)g_part;
    float s = 0.f, ss = 0.f;
#pragma unroll 8
    for (int blk = g; blk < nblk; blk += 8) {
        float2 v = part2[(b * 512 + blk) * 256 + o];
        s += v.x; ss += v.y;
    }
    __shared__ float rs[256], rss[256];
    rs[threadIdx.x] = s; rss[threadIdx.x] = ss;
    __syncthreads();
    if (threadIdx.x < 32) {
#pragma unroll
        for (int m = 1; m < 8; m++) {
            s += rs[threadIdx.x + m * 32]; ss += rss[threadIdx.x + m * 32];
        }
        float mean = s * inv_cnt;
        float var = ss * inv_cnt - mean * mean;
        var = fmaxf(var, 0.f);
        float rstd = rsqrtf(var + 1e-5f);
        g_ms[(b * 256 + o) * 2] = mean;
        g_ms[(b * 256 + o) * 2 + 1] = rstd;
    }
}

// ---------------- norm + lrelu in place, fused next-layer sq -----------------
__global__ void normfin_sq(int O4, int ooff) {
    PDL_SYNC();
    int b = blockIdx.y;
    int w = threadIdx.x >> 5, l = threadIdx.x & 31;
    int row = blockIdx.x * 8 + w;
    float* base = g_feats + ((size_t)b * NN + row) * FTOT + ooff;
    const float2* ms2 = (const float2*)g_ms + b * 256;
    float ssq = 0.f;
    for (int c4 = l; c4 < O4; c4 += 32) {
        int o = c4 * 4;
        float4 v = *(float4*)(base + o);
        float2 m0 = ms2[o], m1 = ms2[o + 1], m2 = ms2[o + 2], m3 = ms2[o + 3];
        v.x = (v.x - m0.x) * m0.y; v.x = (v.x < 0.f) ? 0.2f * v.x : v.x;
        v.y = (v.y - m1.x) * m1.y; v.y = (v.y < 0.f) ? 0.2f * v.y : v.y;
        v.z = (v.z - m2.x) * m2.y; v.z = (v.z < 0.f) ? 0.2f * v.z : v.z;
        v.w = (v.w - m3.x) * m3.y; v.w = (v.w < 0.f) ? 0.2f * v.w : v.w;
        *(float4*)(base + o) = v;
        ssq = fmaf(v.x, v.x, ssq); ssq = fmaf(v.y, v.y, ssq);
        ssq = fmaf(v.z, v.z, ssq); ssq = fmaf(v.w, v.w, ssq);
    }
#pragma unroll
    for (int off = 16; off; off >>= 1) ssq += __shfl_xor_sync(0xffffffffu, ssq, off);
    if (l == 0) g_sq[b * NN + row] = ssq;
}

// ---------------- head: f = feats @ Wh^T (transposed weights) ----------------
__global__ void fconv() {
    PDL_SYNC();
    int b = blockIdx.y, blk = blockIdx.x, o = threadIdx.x;
    __shared__ float4 sf4[8 * 120];
    float* sf = (float*)sf4;
    int i0 = blk * 8;
    for (int r = 0; r < 8; r++)
        for (int c = o; c < 480; c += 128)
            sf[r * 480 + c] = g_feats[((size_t)b * NN + i0 + r) * FTOT + c];
    __syncthreads();
    float acc[8];
#pragma unroll
    for (int r = 0; r < 8; r++) acc[r] = 0.f;
    for (int c4 = 0; c4 < 120; c4++) {
        int c = c4 * 4;
        float w0 = g_WhT[(c + 0) * 128 + o];
        float w1 = g_WhT[(c + 1) * 128 + o];
        float w2 = g_WhT[(c + 2) * 128 + o];
        float w3 = g_WhT[(c + 3) * 128 + o];
#pragma unroll
        for (int r = 0; r < 8; r++) {
            float4 xv = sf4[r * 120 + c4];
            acc[r] = fmaf(xv.x, w0, fmaf(xv.y, w1,
                     fmaf(xv.z, w2, fmaf(xv.w, w3, acc[r]))));
        }
    }
    float s = 0.f, ss = 0.f;
#pragma unroll
    for (int r = 0; r < 8; r++) {
        g_f[((size_t)b * NN + i0 + r) * 128 + o] = acc[r];
        s += acc[r];
        ss = fmaf(acc[r], acc[r], ss);
    }
    int p = ((b * 512 + blk) * 256 + o) * 2;
    g_part[p] = s; g_part[p + 1] = ss;
}

// ---------------- partial max over N of lrelu(norm(f)) -----------------------
__global__ void fpmax_k() {
    PDL_SYNC();
    int b = blockIdx.y, blk = blockIdx.x, o = threadIdx.x;
    float mean = g_ms[(b * 256 + o) * 2];
    float rstd = g_ms[(b * 256 + o) * 2 + 1];
    float m = -FLT_MAX;
    int i0 = blk * 64;
#pragma unroll 8
    for (int i = i0; i < i0 + 64; i++) {
        float v = (g_f[((size_t)b * NN + i) * 128 + o] - mean) * rstd;
        v = (v < 0.f) ? 0.2f * v : v;
        m = fmaxf(m, v);
    }
    g_pmax[(b * 32 + blk) * 128 + o] = m;
}

// ---------------- final: pool, fc1, row-norm, lrelu, fc2 ---------------------
__global__ void head_k(const float* __restrict__ fc1w, const float* __restrict__ fc1b,
                       const float* __restrict__ fc2w, const float* __restrict__ fc2b,
                       float* __restrict__ out) {
    PDL_SYNC();
    int b = blockIdx.x, o = threadIdx.x;
    __shared__ float sg[128], sh[128], r1[128], r2[128];
    float m = -FLT_MAX;
#pragma unroll
    for (int blk = 0; blk < 32; blk++)
        m = fmaxf(m, g_pmax[(b * 32 + blk) * 128 + o]);
    sg[o] = m;
    __syncthreads();
    float acc = fc1b[o];
#pragma unroll 8
    for (int c = 0; c < 128; c++) acc = fmaf(fc1w[o * 128 + c], sg[c], acc);
    r1[o] = acc;
    r2[o] = acc * acc;
    __syncthreads();
    for (int s = 64; s > 0; s >>= 1) {
        if (o < s) { r1[o] += r1[o + s]; r2[o] += r2[o + s]; }
        __syncthreads();
    }
    float mean = r1[0] * (1.f / 128.f);
    float var = r2[0] * (1.f / 128.f) - mean * mean;
    float rstd = rsqrtf(fmaxf(var, 0.f) + 1e-5f);
    float v = (acc - mean) * rstd;
    v = (v < 0.f) ? 0.2f * v : v;
    sh[o] = v;
    __syncthreads();
    float outv = fc2b[o];
#pragma unroll 8
    for (int c = 0; c < 128; c++) outv = fmaf(fc2w[o * 128 + c], sh[c], outv);
    out[b * 128 + o] = outv;
}

// ---------------- host-side PDL launch helper --------------------------------
template <typename K, typename... Args>
static void launch_pdl(K kernel, dim3 grid, dim3 block, size_t smem, Args... args) {
    cudaLaunchConfig_t cfg = {};
    cfg.gridDim = grid;
    cfg.blockDim = block;
    cfg.dynamicSmemBytes = smem;
    cfg.stream = 0;
    cudaLaunchAttribute attr[1];
    attr[0].id = cudaLaunchAttributeProgrammaticStreamSerialization;
    attr[0].val.programmaticStreamSerializationAllowed = 1;
    cfg.attrs = attr;
    cfg.numAttrs = 1;
    cudaLaunchKernelEx(&cfg, kernel, args...);
}

// -----------------------------------------------------------------------------
extern "C" void kernel_launch(void* const* d_in, const int* in_sizes, int n_in,
                              void* d_out, int out_size) {
    (void)in_sizes; (void)n_in; (void)out_size;
    const float* x    = (const float*)d_in[0];
    const float* W0   = (const float*)d_in[2];
    const float* W1   = (const float*)d_in[3];
    const float* W2   = (const float*)d_in[4];
    const float* W3   = (const float*)d_in[5];
    const float* Wh   = (const float*)d_in[6];
    const float* fc1w = (const float*)d_in[7];
    const float* fc1b = (const float*)d_in[8];
    const float* fc2w = (const float*)d_in[9];
    const float* fc2b = (const float*)d_in[10];

    const int Cin[4]  = {3, 32, 64, 128};
    const int Oo[4]   = {32, 64, 128, 256};
    const int Olg[4]  = {5, 6, 7, 8};
    const int C4lg[4] = {0, 3, 4, 5};
    const int coff[4] = {0, 0, 32, 96};
    const int ooff[4] = {0, 32, 96, 224};
    const int woff[4] = {0, 96, 2144, 10336};
    const int RPB[4]  = {8, 8, 4, 4};
    const float invNK = 1.f / (float)(NN * KK);

    static int smem_set = 0;
    if (!smem_set) {
        cudaFuncSetAttribute(select_pq, cudaFuncAttributeMaxDynamicSharedMemorySize,
                             65536);
        smem_set = 1;
    }

    for (int l = 0; l < 4; l++) {
        if (l == 0) {
            launch_pdl(dist_small, dim3(528, 1, BB), dim3(256), 0, x);
        } else {
            launch_pdl(dist_gemm, dim3(136, 1, BB), dim3(256), 0, Cin[l], coff[l]);
        }
        int R = 16 * (256 >> Olg[l]);
        int npq = (l == 0) ? 512 : (BB * NN) / R;
        int nprep = (l == 0) ? 408 : 0;
        launch_pdl(select_pq, dim3(512 + npq + nprep), dim3(256), 65536,
                   l, Cin[l], Oo[l], Olg[l], C4lg[l], coff[l], woff[l], R,
                   x, W0, W1, W2, W3, Wh);
        int ngs = NN / RPB[l];
        launch_pdl(gstat, dim3(ngs, BB), dim3(256), 0, Olg[l], Oo[l], ooff[l], RPB[l]);
        launch_pdl(stats_final, dim3(Oo[l] / 32, BB), dim3(256), 0, ngs, invNK);
        launch_pdl(normfin_sq, dim3(NN / 8, BB), dim3(256), 0, Oo[l] / 4, ooff[l]);
    }
    launch_pdl(fconv, dim3(256, BB), dim3(128), 0);
    launch_pdl(stats_final, dim3(4, BB), dim3(256), 0, 256, 1.f / (float)NN);
    launch_pdl(fpmax_k, dim3(32, BB), dim3(128), 0);
    launch_pdl(head_k, dim3(BB), dim3(128), 0, fc1w, fc1b, fc2w, fc2b, (float*)d_out);
}